// round 3
// baseline (speedup 1.0000x reference)
#include <cuda_runtime.h>

#define BB 256
#define DD 1024
#define LOG2E 1.4426950408889634f

// scratch for Q, K, V (3 MB) — __device__ global per allocation rules
__device__ float g_QKV[3 * BB * DD];

__device__ __forceinline__ float ex2f(float x) {
    float y; asm("ex2.approx.ftz.f32 %0, %1;" : "=f"(y) : "f"(x)); return y;
}
__device__ __forceinline__ unsigned long long pk2(float lo, float hi) {
    unsigned long long r; asm("mov.b64 %0, {%1,%2};" : "=l"(r) : "f"(lo), "f"(hi)); return r;
}
__device__ __forceinline__ void upk2(unsigned long long v, float &lo, float &hi) {
    asm("mov.b64 {%0,%1}, %2;" : "=f"(lo), "=f"(hi) : "l"(v));
}
__device__ __forceinline__ unsigned long long ffma2(unsigned long long a, unsigned long long b, unsigned long long c) {
    unsigned long long d;
    asm("fma.rn.f32x2 %0, %1, %2, %3;" : "=l"(d) : "l"(a), "l"(b), "l"(c));
    return d;
}

// ---------------------------------------------------------------------------
// Kernel 1: QKV projection GEMMs.  out[b,n] = sum_k x[b,k]*W[n,k] + bias[n]
// Tile 32(m) x 64(n), K-step 32, 128 threads, 4m x 4n outputs/thread.
// A-tile stored PRE-DUPLICATED as float2 (a,a) so the inner loop is pure
// 3x LDS.128 + 8x FFMA2 (no packing MOVs). Double buffered.
// grid = (B/32=8, D/64=16, 3) = 384 blocks -> all co-resident on 148 SMs.
// ---------------------------------------------------------------------------
#define TM 32
#define TN 64
#define TK 32
#define GTH 128

__global__ __launch_bounds__(GTH) void gemm_qkv_kernel(
    const float* __restrict__ x,
    const float* __restrict__ Wq, const float* __restrict__ bq,
    const float* __restrict__ Wk, const float* __restrict__ bk,
    const float* __restrict__ Wv, const float* __restrict__ bv)
{
    const int z = blockIdx.z;
    const float* W    = (z == 0) ? Wq : (z == 1) ? Wk : Wv;
    const float* bias = (z == 0) ? bq : (z == 1) ? bk : bv;
    float* out = g_QKV + z * (BB * DD);

    __shared__ __align__(16) float2 xs[2][TK][TM];  // duplicated (a,a) pairs, 16KB
    __shared__ __align__(16) float  ws[2][TK][TN];  // 16KB

    const int t  = threadIdx.x;
    const int m0 = blockIdx.x * TM;
    const int n0 = blockIdx.y * TN;

    // x loader: row r (0..31), k-group of 8
    const int xr  = t & 31;
    const int xk0 = (t >> 5) * 8;          // 0,8,16,24
    // W loader: row n (0..63), k-group of 16
    const int wn  = t & 63;
    const int wk0 = (t >> 6) * 16;         // 0,16

    // compute mapping: 16(tx,n) x 8(ty,m), 4x4 per thread
    const int tx = t & 15;
    const int ty = t >> 4;

    unsigned long long acc[4][2];
#pragma unroll
    for (int i = 0; i < 4; i++) { acc[i][0] = pk2(0.f, 0.f); acc[i][1] = pk2(0.f, 0.f); }

    const float* xp = &x[(m0 + xr) * DD + xk0];
    const float* wp = &W[(n0 + wn) * DD + wk0];

    float4 ax0, ax1, aw0, aw1, aw2, aw3;
    ax0 = *(const float4*)(xp);      ax1 = *(const float4*)(xp + 4);
    aw0 = *(const float4*)(wp);      aw1 = *(const float4*)(wp + 4);
    aw2 = *(const float4*)(wp + 8);  aw3 = *(const float4*)(wp + 12);

    int buf = 0;
#pragma unroll
    for (int j = 0; j < 4; j++) {
        xs[0][xk0 + j][xr]     = make_float2(((const float*)&ax0)[j], ((const float*)&ax0)[j]);
        xs[0][xk0 + 4 + j][xr] = make_float2(((const float*)&ax1)[j], ((const float*)&ax1)[j]);
        ws[0][wk0 + j][wn]      = ((const float*)&aw0)[j];
        ws[0][wk0 + 4 + j][wn]  = ((const float*)&aw1)[j];
        ws[0][wk0 + 8 + j][wn]  = ((const float*)&aw2)[j];
        ws[0][wk0 + 12 + j][wn] = ((const float*)&aw3)[j];
    }
    __syncthreads();

    const int NT = DD / TK;  // 32
    for (int kt = 0; kt < NT; kt++) {
        if (kt + 1 < NT) {
            const float* px = xp + (kt + 1) * TK;
            const float* pw = wp + (kt + 1) * TK;
            ax0 = *(const float4*)(px);      ax1 = *(const float4*)(px + 4);
            aw0 = *(const float4*)(pw);      aw1 = *(const float4*)(pw + 4);
            aw2 = *(const float4*)(pw + 8);  aw3 = *(const float4*)(pw + 12);
        }
#pragma unroll
        for (int kk = 0; kk < TK; kk++) {
            const float2* xrow = &xs[buf][kk][ty * 4];
            ulonglong2 a01 = *(const ulonglong2*)(xrow);        // (a0,a0),(a1,a1)
            ulonglong2 a23 = *(const ulonglong2*)(xrow + 2);    // (a2,a2),(a3,a3)
            ulonglong2 bp  = *(const ulonglong2*)&ws[buf][kk][tx * 4]; // (b0,b1),(b2,b3)
            acc[0][0] = ffma2(a01.x, bp.x, acc[0][0]);  acc[0][1] = ffma2(a01.x, bp.y, acc[0][1]);
            acc[1][0] = ffma2(a01.y, bp.x, acc[1][0]);  acc[1][1] = ffma2(a01.y, bp.y, acc[1][1]);
            acc[2][0] = ffma2(a23.x, bp.x, acc[2][0]);  acc[2][1] = ffma2(a23.x, bp.y, acc[2][1]);
            acc[3][0] = ffma2(a23.y, bp.x, acc[3][0]);  acc[3][1] = ffma2(a23.y, bp.y, acc[3][1]);
        }
        if (kt + 1 < NT) {
            __syncthreads();
            buf ^= 1;
#pragma unroll
            for (int j = 0; j < 4; j++) {
                xs[buf][xk0 + j][xr]     = make_float2(((const float*)&ax0)[j], ((const float*)&ax0)[j]);
                xs[buf][xk0 + 4 + j][xr] = make_float2(((const float*)&ax1)[j], ((const float*)&ax1)[j]);
                ws[buf][wk0 + j][wn]      = ((const float*)&aw0)[j];
                ws[buf][wk0 + 4 + j][wn]  = ((const float*)&aw1)[j];
                ws[buf][wk0 + 8 + j][wn]  = ((const float*)&aw2)[j];
                ws[buf][wk0 + 12 + j][wn] = ((const float*)&aw3)[j];
            }
            __syncthreads();
        }
    }

    float4 bb = *(const float4*)&bias[n0 + tx * 4];
#pragma unroll
    for (int i = 0; i < 4; i++) {
        float r0, r1, r2, r3;
        upk2(acc[i][0], r0, r1);
        upk2(acc[i][1], r2, r3);
        float4 o;
        o.x = r0 + bb.x; o.y = r1 + bb.y; o.z = r2 + bb.z; o.w = r3 + bb.w;
        *(float4*)&out[(m0 + ty * 4 + i) * DD + n0 + tx * 4] = o;
    }
}

// ---------------------------------------------------------------------------
// Kernel 2: per-(b,i) scalar-softmax attention + residual.
//   logits_j = (Q[b,i]/scale) * K[b,j];  attn = softmax_j;  att = attn . V[b,:]
//   out[b,i] = att + x[b,i]     (RMSNorm applied by kernel 3, in-place)
// grid = 1024 blocks (b x i-quarter), 256 threads, one i per thread.
// K,V staged in shared as float2; inner loop is MUFU(EX2)-bound (at pipe roofline).
// ---------------------------------------------------------------------------
__global__ __launch_bounds__(256) void attn_kernel(
    const float* __restrict__ x,
    const float* __restrict__ scale_p,
    float* __restrict__ out)
{
    const int b     = blockIdx.x >> 2;
    const int ibase = (blockIdx.x & 3) << 8;
    const int t     = threadIdx.x;

    __shared__ float2 kv[DD];
    __shared__ float redmx[8], redmn[8];

    const float* Kp = g_QKV + BB * DD + b * DD;
    const float* Vp = g_QKV + 2 * BB * DD + b * DD;

    float mx = -1e30f, mn = 1e30f;
#pragma unroll
    for (int j = t; j < DD; j += 256) {
        float kx = Kp[j];
        float vy = Vp[j];
        kv[j] = make_float2(kx, vy);
        mx = fmaxf(mx, kx);
        mn = fminf(mn, kx);
    }
#pragma unroll
    for (int o = 16; o > 0; o >>= 1) {
        mx = fmaxf(mx, __shfl_xor_sync(0xFFFFFFFFu, mx, o));
        mn = fminf(mn, __shfl_xor_sync(0xFFFFFFFFu, mn, o));
    }
    if ((t & 31) == 0) { redmx[t >> 5] = mx; redmn[t >> 5] = mn; }
    __syncthreads();
    mx = redmx[0]; mn = redmn[0];
#pragma unroll
    for (int w = 1; w < 8; w++) { mx = fmaxf(mx, redmx[w]); mn = fminf(mn, redmn[w]); }

    const int   i   = ibase + t;
    const float cs  = LOG2E / scale_p[0];
    const float c2  = g_QKV[b * DD + i] * cs;     // Q scaled into log2 domain
    const float m2  = (c2 >= 0.f) ? c2 * mx : c2 * mn;   // row max in log2 domain
    const float nm2 = -m2;

    float s  = 0.f;
    float dn = 0.f;
#pragma unroll 8
    for (int j = 0; j < DD; j++) {
        float2 kvj = kv[j];                        // broadcast LDS.64
        float  e   = ex2f(__fmaf_rn(c2, kvj.x, nm2));
        s  += e;
        dn  = __fmaf_rn(e, kvj.y, dn);
    }

    out[b * DD + i] = dn / s + x[b * DD + i];
}

// ---------------------------------------------------------------------------
// Kernel 3: in-place RMSNorm over each row of out. grid = 256, 256 threads.
// ---------------------------------------------------------------------------
__global__ __launch_bounds__(256) void rmsnorm_kernel(
    float* __restrict__ out, const float* __restrict__ nw)
{
    const int b = blockIdx.x;
    const int t = threadIdx.x;
    __shared__ float red[8];

    float4 h = *(const float4*)&out[b * DD + t * 4];
    float local = h.x * h.x + h.y * h.y + h.z * h.z + h.w * h.w;
#pragma unroll
    for (int o = 16; o > 0; o >>= 1) local += __shfl_xor_sync(0xFFFFFFFFu, local, o);
    if ((t & 31) == 0) red[t >> 5] = local;
    __syncthreads();
    float tot = 0.f;
#pragma unroll
    for (int w = 0; w < 8; w++) tot += red[w];

    float r = rsqrtf(tot * (1.0f / DD) + 1e-6f);
    float4 w4 = *(const float4*)&nw[t * 4];
    float4 o;
    o.x = h.x * r * w4.x;
    o.y = h.y * r * w4.y;
    o.z = h.z * r * w4.z;
    o.w = h.w * r * w4.w;
    *(float4*)&out[b * DD + t * 4] = o;
}

extern "C" void kernel_launch(void* const* d_in, const int* in_sizes, int n_in,
                              void* d_out, int out_size)
{
    const float* x     = (const float*)d_in[0];
    const float* Wq    = (const float*)d_in[1];
    const float* bq    = (const float*)d_in[2];
    const float* Wk    = (const float*)d_in[3];
    const float* bk    = (const float*)d_in[4];
    const float* Wv    = (const float*)d_in[5];
    const float* bv    = (const float*)d_in[6];
    const float* scale = (const float*)d_in[7];
    const float* nw    = (const float*)d_in[8];
    float* out = (float*)d_out;

    dim3 ggrid(BB / TM, DD / TN, 3);
    gemm_qkv_kernel<<<ggrid, GTH>>>(x, Wq, bq, Wk, bk, Wv, bv);
    attn_kernel<<<BB * 4, 256>>>(x, scale, out);
    rmsnorm_kernel<<<BB, 256>>>(out, nw);
}

// round 5
// speedup vs baseline: 1.1498x; 1.1498x over previous
#include <cuda_runtime.h>

#define BB 256
#define DD 1024
#define LOG2E 1.4426950408889634f
#define KHALF 512

// scratch: two K-split partial buffers for Q,K,V (3 MB each)
__device__ float g_P0[3 * BB * DD];
__device__ float g_P1[3 * BB * DD];

__device__ __forceinline__ float ex2f(float x) {
    float y; asm("ex2.approx.ftz.f32 %0, %1;" : "=f"(y) : "f"(x)); return y;
}
__device__ __forceinline__ unsigned long long pk2(float lo, float hi) {
    unsigned long long r; asm("mov.b64 %0, {%1,%2};" : "=l"(r) : "f"(lo), "f"(hi)); return r;
}
__device__ __forceinline__ void upk2(unsigned long long v, float &lo, float &hi) {
    asm("mov.b64 {%0,%1}, %2;" : "=f"(lo), "=f"(hi) : "l"(v));
}
__device__ __forceinline__ unsigned long long ffma2(unsigned long long a, unsigned long long b, unsigned long long c) {
    unsigned long long d;
    asm("fma.rn.f32x2 %0, %1, %2, %3;" : "=l"(d) : "l"(a), "l"(b), "l"(c));
    return d;
}

// ---------------------------------------------------------------------------
// Kernel 1: QKV projection partial GEMMs with split-K=2.
//   partial[b,n] = sum_{k in half} x[b,k]*W[n,k]          (bias added later)
// Tile 64(m) x 64(n) x K-step 32, 256 threads, 4m x 4n per thread via FFMA2.
// A-tile pre-duplicated float2 (broadcast side); B-tile plain floats.
// grid = (4, 16, 6): z = ksplit*3 + gemm_id. 384 blocks x 8 warps
//   -> ~21 warps/SM resident, 2.6 waves.
// ---------------------------------------------------------------------------
#define TM 64
#define TN 64
#define TK 32
#define GTH 256

__global__ __launch_bounds__(GTH) void gemm_qkv_kernel(
    const float* __restrict__ x,
    const float* __restrict__ Wq,
    const float* __restrict__ Wk,
    const float* __restrict__ Wv)
{
    const int z  = blockIdx.z;
    const int g  = z % 3;        // 0=Q, 1=K, 2=V
    const int ks = z / 3;        // k-split half
    const float* W = (g == 0) ? Wq : (g == 1) ? Wk : Wv;
    float* out = ((ks == 0) ? g_P0 : g_P1) + g * (BB * DD);

    __shared__ __align__(16) float2 xs[2][TK][TM];  // duplicated (a,a), 32KB
    __shared__ __align__(16) float  ws[2][TK][TN];  // 16KB

    const int t  = threadIdx.x;
    const int m0 = blockIdx.x * TM;
    const int n0 = blockIdx.y * TN;
    const int k0 = ks * KHALF;

    // loaders: 256 threads fill 64 rows x 32 k (8 k per thread)
    const int lr  = t & 63;            // row in tile (m for x, n for W)
    const int lk0 = (t >> 6) * 8;      // 0,8,16,24

    // compute map: 16(tx,n) x 16(ty,m), 4x4 per thread
    const int tx = t & 15;
    const int ty = t >> 4;

    unsigned long long acc[4][2];
#pragma unroll
    for (int i = 0; i < 4; i++) { acc[i][0] = pk2(0.f, 0.f); acc[i][1] = pk2(0.f, 0.f); }

    const float* xp = &x[(m0 + lr) * DD + k0 + lk0];
    const float* wp = &W[(n0 + lr) * DD + k0 + lk0];

    float4 ax0, ax1, aw0, aw1;
    ax0 = *(const float4*)(xp);      ax1 = *(const float4*)(xp + 4);
    aw0 = *(const float4*)(wp);      aw1 = *(const float4*)(wp + 4);

    int buf = 0;
#pragma unroll
    for (int j = 0; j < 4; j++) {
        xs[0][lk0 + j][lr]     = make_float2(((const float*)&ax0)[j], ((const float*)&ax0)[j]);
        xs[0][lk0 + 4 + j][lr] = make_float2(((const float*)&ax1)[j], ((const float*)&ax1)[j]);
        ws[0][lk0 + j][lr]     = ((const float*)&aw0)[j];
        ws[0][lk0 + 4 + j][lr] = ((const float*)&aw1)[j];
    }
    __syncthreads();

    const int NT = KHALF / TK;  // 16
    for (int kt = 0; kt < NT; kt++) {
        if (kt + 1 < NT) {
            const float* px = xp + (kt + 1) * TK;
            const float* pw = wp + (kt + 1) * TK;
            ax0 = *(const float4*)(px);  ax1 = *(const float4*)(px + 4);
            aw0 = *(const float4*)(pw);  aw1 = *(const float4*)(pw + 4);
        }
#pragma unroll
        for (int kk = 0; kk < TK; kk++) {
            const float2* xrow = &xs[buf][kk][ty * 4];
            ulonglong2 a01 = *(const ulonglong2*)(xrow);        // (a0,a0),(a1,a1)
            ulonglong2 a23 = *(const ulonglong2*)(xrow + 2);    // (a2,a2),(a3,a3)
            ulonglong2 bp  = *(const ulonglong2*)&ws[buf][kk][tx * 4]; // (b0,b1),(b2,b3)
            acc[0][0] = ffma2(a01.x, bp.x, acc[0][0]);  acc[0][1] = ffma2(a01.x, bp.y, acc[0][1]);
            acc[1][0] = ffma2(a01.y, bp.x, acc[1][0]);  acc[1][1] = ffma2(a01.y, bp.y, acc[1][1]);
            acc[2][0] = ffma2(a23.x, bp.x, acc[2][0]);  acc[2][1] = ffma2(a23.x, bp.y, acc[2][1]);
            acc[3][0] = ffma2(a23.y, bp.x, acc[3][0]);  acc[3][1] = ffma2(a23.y, bp.y, acc[3][1]);
        }
        if (kt + 1 < NT) {
            __syncthreads();
            buf ^= 1;
#pragma unroll
            for (int j = 0; j < 4; j++) {
                xs[buf][lk0 + j][lr]     = make_float2(((const float*)&ax0)[j], ((const float*)&ax0)[j]);
                xs[buf][lk0 + 4 + j][lr] = make_float2(((const float*)&ax1)[j], ((const float*)&ax1)[j]);
                ws[buf][lk0 + j][lr]     = ((const float*)&aw0)[j];
                ws[buf][lk0 + 4 + j][lr] = ((const float*)&aw1)[j];
            }
            __syncthreads();
        }
    }

#pragma unroll
    for (int i = 0; i < 4; i++) {
        float r0, r1, r2, r3;
        upk2(acc[i][0], r0, r1);
        upk2(acc[i][1], r2, r3);
        float4 o; o.x = r0; o.y = r1; o.z = r2; o.w = r3;
        *(float4*)&out[(m0 + ty * 4 + i) * DD + n0 + tx * 4] = o;
    }
}

// ---------------------------------------------------------------------------
// Kernel 2: per-(b,i) scalar-softmax attention + residual.
// Fuses the split-K reduction and the QKV bias adds into the load phase.
// grid = 1024 blocks (b x i-quarter), 256 threads, one i per thread.
// Inner loop is MUFU(EX2)-bound (pipe roofline).
// ---------------------------------------------------------------------------
__global__ __launch_bounds__(256) void attn_kernel(
    const float* __restrict__ x,
    const float* __restrict__ scale_p,
    const float* __restrict__ bq,
    const float* __restrict__ bk,
    const float* __restrict__ bv,
    float* __restrict__ out)
{
    const int b     = blockIdx.x >> 2;
    const int ibase = (blockIdx.x & 3) << 8;
    const int t     = threadIdx.x;

    __shared__ float2 kv[DD];
    __shared__ float redmx[8], redmn[8];

    const float* K0 = g_P0 + BB * DD + b * DD;
    const float* K1 = g_P1 + BB * DD + b * DD;
    const float* V0 = g_P0 + 2 * BB * DD + b * DD;
    const float* V1 = g_P1 + 2 * BB * DD + b * DD;

    float mx = -1e30f, mn = 1e30f;
#pragma unroll
    for (int j = t; j < DD; j += 256) {
        float kx = K0[j] + K1[j] + bk[j];
        float vy = V0[j] + V1[j] + bv[j];
        kv[j] = make_float2(kx, vy);
        mx = fmaxf(mx, kx);
        mn = fminf(mn, kx);
    }
#pragma unroll
    for (int o = 16; o > 0; o >>= 1) {
        mx = fmaxf(mx, __shfl_xor_sync(0xFFFFFFFFu, mx, o));
        mn = fminf(mn, __shfl_xor_sync(0xFFFFFFFFu, mn, o));
    }
    if ((t & 31) == 0) { redmx[t >> 5] = mx; redmn[t >> 5] = mn; }
    __syncthreads();
    mx = redmx[0]; mn = redmn[0];
#pragma unroll
    for (int w = 1; w < 8; w++) { mx = fmaxf(mx, redmx[w]); mn = fminf(mn, redmn[w]); }

    const int   i   = ibase + t;
    const float cs  = LOG2E / scale_p[0];
    const float q   = g_P0[b * DD + i] + g_P1[b * DD + i] + bq[i];
    const float c2  = q * cs;                              // Q scaled into log2 domain
    const float m2  = (c2 >= 0.f) ? c2 * mx : c2 * mn;     // row max in log2 domain
    const float nm2 = -m2;

    float s  = 0.f;
    float dn = 0.f;
#pragma unroll 8
    for (int j = 0; j < DD; j++) {
        float2 kvj = kv[j];                        // broadcast LDS.64
        float  e   = ex2f(__fmaf_rn(c2, kvj.x, nm2));
        s  += e;
        dn  = __fmaf_rn(e, kvj.y, dn);
    }

    out[b * DD + i] = dn / s + x[b * DD + i];
}

// ---------------------------------------------------------------------------
// Kernel 3: in-place RMSNorm over each row of out. grid = 256, 256 threads.
// ---------------------------------------------------------------------------
__global__ __launch_bounds__(256) void rmsnorm_kernel(
    float* __restrict__ out, const float* __restrict__ nw)
{
    const int b = blockIdx.x;
    const int t = threadIdx.x;
    __shared__ float red[8];

    float4 h = *(const float4*)&out[b * DD + t * 4];
    float local = h.x * h.x + h.y * h.y + h.z * h.z + h.w * h.w;
#pragma unroll
    for (int o = 16; o > 0; o >>= 1) local += __shfl_xor_sync(0xFFFFFFFFu, local, o);
    if ((t & 31) == 0) red[t >> 5] = local;
    __syncthreads();
    float tot = 0.f;
#pragma unroll
    for (int w = 0; w < 8; w++) tot += red[w];

    float r = rsqrtf(tot * (1.0f / DD) + 1e-6f);
    float4 w4 = *(const float4*)&nw[t * 4];
    float4 o;
    o.x = h.x * r * w4.x;
    o.y = h.y * r * w4.y;
    o.z = h.z * r * w4.z;
    o.w = h.w * r * w4.w;
    *(float4*)&out[b * DD + t * 4] = o;
}

extern "C" void kernel_launch(void* const* d_in, const int* in_sizes, int n_in,
                              void* d_out, int out_size)
{
    const float* x     = (const float*)d_in[0];
    const float* Wq    = (const float*)d_in[1];
    const float* bq    = (const float*)d_in[2];
    const float* Wk    = (const float*)d_in[3];
    const float* bk    = (const float*)d_in[4];
    const float* Wv    = (const float*)d_in[5];
    const float* bv    = (const float*)d_in[6];
    const float* scale = (const float*)d_in[7];
    const float* nw    = (const float*)d_in[8];
    float* out = (float*)d_out;

    dim3 ggrid(BB / TM, DD / TN, 6);   // z = ksplit*3 + gemm_id
    gemm_qkv_kernel<<<ggrid, GTH>>>(x, Wq, Wk, Wv);
    attn_kernel<<<BB * 4, 256>>>(x, scale, bq, bk, bv, out);
    rmsnorm_kernel<<<BB, 256>>>(out, nw);
}

// round 7
// speedup vs baseline: 1.6148x; 1.4044x over previous
#include <cuda_runtime.h>

#define BB 256
#define DD 1024
#define LOG2E 1.4426950408889634f

// scratch: three split-K partial buffers for Q,K,V (3 MB each)
__device__ float g_P0[3 * BB * DD];
__device__ float g_P1[3 * BB * DD];
__device__ float g_P2[3 * BB * DD];

__device__ __forceinline__ float ex2f(float x) {
    float y; asm("ex2.approx.ftz.f32 %0, %1;" : "=f"(y) : "f"(x)); return y;
}
__device__ __forceinline__ unsigned long long pk2(float lo, float hi) {
    unsigned long long r; asm("mov.b64 %0, {%1,%2};" : "=l"(r) : "f"(lo), "f"(hi)); return r;
}
__device__ __forceinline__ void upk2(unsigned long long v, float &lo, float &hi) {
    asm("mov.b64 {%0,%1}, %2;" : "=f"(lo), "=f"(hi) : "l"(v));
}
__device__ __forceinline__ unsigned long long ffma2(unsigned long long a, unsigned long long b, unsigned long long c) {
    unsigned long long d;
    asm("fma.rn.f32x2 %0, %1, %2, %3;" : "=l"(d) : "l"(a), "l"(b), "l"(c));
    return d;
}

// ---------------------------------------------------------------------------
// Kernel 1: QKV partial GEMMs, split-K=3 (352/352/320).
// Tile 128(m) x 128(n) x 16(k), 256 threads, 8m x 8n per thread via FFMA2.
// A and B plain floats in smem (1 B/FMA crossbar); pk2 MOVs ride the ALU pipe.
// Per-thread m,n = two 4-wide chunks 64 apart -> all LDS.128 conflict-free.
// grid = (2, 8, 9): z = ks*3 + gemm_id -> 144 blocks = one full wave.
// ---------------------------------------------------------------------------
#define TM 128
#define TN 128
#define TK 16
#define GTH 256

__global__ __launch_bounds__(GTH) void gemm_qkv_kernel(
    const float* __restrict__ x,
    const float* __restrict__ Wq,
    const float* __restrict__ Wk,
    const float* __restrict__ Wv)
{
    const int z  = blockIdx.z;
    const int g  = z % 3;        // 0=Q, 1=K, 2=V
    const int ks = z / 3;        // k-split index
    const float* W = (g == 0) ? Wq : (g == 1) ? Wk : Wv;
    float* out = ((ks == 0) ? g_P0 : (ks == 1) ? g_P1 : g_P2) + g * (BB * DD);
    const int k0 = ks * 352;
    const int NT = (ks < 2) ? 22 : 20;   // k-tiles of 16

    __shared__ __align__(16) float xs[2][TK][TM];  // 16KB
    __shared__ __align__(16) float ws[2][TK][TN];  // 16KB

    const int t  = threadIdx.x;
    const int m0 = blockIdx.x * TM;
    const int n0 = blockIdx.y * TN;

    // loaders: 256 threads fill 128 rows x 16 k (8 consecutive k per thread)
    const int lr  = t & 127;           // row (m for x, n for W)
    const int lk0 = (t >> 7) * 8;      // 0 or 8

    // compute map: 16(tx) x 16(ty); per-thread n = tx*4+{0..3} & 64+tx*4+{0..3},
    //                               per-thread m = ty*4+{0..3} & 64+ty*4+{0..3}
    const int tx = t & 15;
    const int ty = t >> 4;

    unsigned long long acc[8][4];
#pragma unroll
    for (int i = 0; i < 8; i++)
#pragma unroll
        for (int j = 0; j < 4; j++) acc[i][j] = pk2(0.f, 0.f);

    const float* xp = &x[(m0 + lr) * DD + k0 + lk0];
    const float* wp = &W[(n0 + lr) * DD + k0 + lk0];

    float4 ax0, ax1, aw0, aw1;
    ax0 = *(const float4*)(xp);  ax1 = *(const float4*)(xp + 4);
    aw0 = *(const float4*)(wp);  aw1 = *(const float4*)(wp + 4);

    int buf = 0;
#pragma unroll
    for (int j = 0; j < 4; j++) {
        xs[0][lk0 + j][lr]     = ((const float*)&ax0)[j];
        xs[0][lk0 + 4 + j][lr] = ((const float*)&ax1)[j];
        ws[0][lk0 + j][lr]     = ((const float*)&aw0)[j];
        ws[0][lk0 + 4 + j][lr] = ((const float*)&aw1)[j];
    }
    __syncthreads();

    for (int kt = 0; kt < NT; kt++) {
        if (kt + 1 < NT) {
            const float* px = xp + (kt + 1) * TK;
            const float* pw = wp + (kt + 1) * TK;
            ax0 = *(const float4*)(px);  ax1 = *(const float4*)(px + 4);
            aw0 = *(const float4*)(pw);  aw1 = *(const float4*)(pw + 4);
        }
#pragma unroll
        for (int kk = 0; kk < TK; kk++) {
            float4 a0 = *(const float4*)&xs[buf][kk][ty * 4];
            float4 a1 = *(const float4*)&xs[buf][kk][64 + ty * 4];
            ulonglong2 b0 = *(const ulonglong2*)&ws[buf][kk][tx * 4];       // (b0,b1),(b2,b3)
            ulonglong2 b1 = *(const ulonglong2*)&ws[buf][kk][64 + tx * 4];
            unsigned long long ad[8];
            ad[0] = pk2(a0.x, a0.x); ad[1] = pk2(a0.y, a0.y);
            ad[2] = pk2(a0.z, a0.z); ad[3] = pk2(a0.w, a0.w);
            ad[4] = pk2(a1.x, a1.x); ad[5] = pk2(a1.y, a1.y);
            ad[6] = pk2(a1.z, a1.z); ad[7] = pk2(a1.w, a1.w);
#pragma unroll
            for (int mi = 0; mi < 8; mi++) {
                acc[mi][0] = ffma2(ad[mi], b0.x, acc[mi][0]);
                acc[mi][1] = ffma2(ad[mi], b0.y, acc[mi][1]);
                acc[mi][2] = ffma2(ad[mi], b1.x, acc[mi][2]);
                acc[mi][3] = ffma2(ad[mi], b1.y, acc[mi][3]);
            }
        }
        if (kt + 1 < NT) {
            __syncthreads();
            buf ^= 1;
#pragma unroll
            for (int j = 0; j < 4; j++) {
                xs[buf][lk0 + j][lr]     = ((const float*)&ax0)[j];
                xs[buf][lk0 + 4 + j][lr] = ((const float*)&ax1)[j];
                ws[buf][lk0 + j][lr]     = ((const float*)&aw0)[j];
                ws[buf][lk0 + 4 + j][lr] = ((const float*)&aw1)[j];
            }
            __syncthreads();
        }
    }

#pragma unroll
    for (int mi = 0; mi < 8; mi++) {
        const int row = m0 + ((mi < 4) ? (ty * 4 + mi) : (64 + ty * 4 + mi - 4));
        float r0, r1, r2, r3;
        float4 o;
        upk2(acc[mi][0], r0, r1);  upk2(acc[mi][1], r2, r3);
        o.x = r0; o.y = r1; o.z = r2; o.w = r3;
        *(float4*)&out[row * DD + n0 + tx * 4] = o;
        upk2(acc[mi][2], r0, r1);  upk2(acc[mi][3], r2, r3);
        o.x = r0; o.y = r1; o.z = r2; o.w = r3;
        *(float4*)&out[row * DD + n0 + 64 + tx * 4] = o;
    }
}

// ---------------------------------------------------------------------------
// Kernel 2: per-(b,i) scalar-softmax attention + residual.
// Fuses the 3-way split-K reduction and QKV bias adds into the load phase.
// grid = 1024 blocks (b x i-quarter), 256 threads; inner loop at MUFU roofline.
// ---------------------------------------------------------------------------
__global__ __launch_bounds__(256) void attn_kernel(
    const float* __restrict__ x,
    const float* __restrict__ scale_p,
    const float* __restrict__ bq,
    const float* __restrict__ bk,
    const float* __restrict__ bv,
    float* __restrict__ out)
{
    const int b     = blockIdx.x >> 2;
    const int ibase = (blockIdx.x & 3) << 8;
    const int t     = threadIdx.x;

    __shared__ float2 kv[DD];
    __shared__ float redmx[8], redmn[8];

    const int koff = BB * DD + b * DD;
    const int voff = 2 * BB * DD + b * DD;

    float mx = -1e30f, mn = 1e30f;
#pragma unroll
    for (int j = t; j < DD; j += 256) {
        float kx = g_P0[koff + j] + g_P1[koff + j] + g_P2[koff + j] + bk[j];
        float vy = g_P0[voff + j] + g_P1[voff + j] + g_P2[voff + j] + bv[j];
        kv[j] = make_float2(kx, vy);
        mx = fmaxf(mx, kx);
        mn = fminf(mn, kx);
    }
#pragma unroll
    for (int o = 16; o > 0; o >>= 1) {
        mx = fmaxf(mx, __shfl_xor_sync(0xFFFFFFFFu, mx, o));
        mn = fminf(mn, __shfl_xor_sync(0xFFFFFFFFu, mn, o));
    }
    if ((t & 31) == 0) { redmx[t >> 5] = mx; redmn[t >> 5] = mn; }
    __syncthreads();
    mx = redmx[0]; mn = redmn[0];
#pragma unroll
    for (int w = 1; w < 8; w++) { mx = fmaxf(mx, redmx[w]); mn = fminf(mn, redmn[w]); }

    const int   i   = ibase + t;
    const int   qi  = b * DD + i;
    const float cs  = LOG2E / scale_p[0];
    const float q   = g_P0[qi] + g_P1[qi] + g_P2[qi] + bq[i];
    const float c2  = q * cs;                              // Q scaled into log2 domain
    const float m2  = (c2 >= 0.f) ? c2 * mx : c2 * mn;     // row max in log2 domain
    const float nm2 = -m2;

    float s  = 0.f;
    float dn = 0.f;
#pragma unroll 8
    for (int j = 0; j < DD; j++) {
        float2 kvj = kv[j];                        // broadcast LDS.64
        float  e   = ex2f(__fmaf_rn(c2, kvj.x, nm2));
        s  += e;
        dn  = __fmaf_rn(e, kvj.y, dn);
    }

    out[b * DD + i] = dn / s + x[b * DD + i];
}

// ---------------------------------------------------------------------------
// Kernel 3: in-place RMSNorm over each row of out. grid = 256, 256 threads.
// ---------------------------------------------------------------------------
__global__ __launch_bounds__(256) void rmsnorm_kernel(
    float* __restrict__ out, const float* __restrict__ nw)
{
    const int b = blockIdx.x;
    const int t = threadIdx.x;
    __shared__ float red[8];

    float4 h = *(const float4*)&out[b * DD + t * 4];
    float local = h.x * h.x + h.y * h.y + h.z * h.z + h.w * h.w;
#pragma unroll
    for (int o = 16; o > 0; o >>= 1) local += __shfl_xor_sync(0xFFFFFFFFu, local, o);
    if ((t & 31) == 0) red[t >> 5] = local;
    __syncthreads();
    float tot = 0.f;
#pragma unroll
    for (int w = 0; w < 8; w++) tot += red[w];

    float r = rsqrtf(tot * (1.0f / DD) + 1e-6f);
    float4 w4 = *(const float4*)&nw[t * 4];
    float4 o;
    o.x = h.x * r * w4.x;
    o.y = h.y * r * w4.y;
    o.z = h.z * r * w4.z;
    o.w = h.w * r * w4.w;
    *(float4*)&out[b * DD + t * 4] = o;
}

extern "C" void kernel_launch(void* const* d_in, const int* in_sizes, int n_in,
                              void* d_out, int out_size)
{
    const float* x     = (const float*)d_in[0];
    const float* Wq    = (const float*)d_in[1];
    const float* bq    = (const float*)d_in[2];
    const float* Wk    = (const float*)d_in[3];
    const float* bk    = (const float*)d_in[4];
    const float* Wv    = (const float*)d_in[5];
    const float* bv    = (const float*)d_in[6];
    const float* scale = (const float*)d_in[7];
    const float* nw    = (const float*)d_in[8];
    float* out = (float*)d_out;

    dim3 ggrid(BB / TM, DD / TN, 9);   // z = ks*3 + gemm_id
    gemm_qkv_kernel<<<ggrid, GTH>>>(x, Wq, Wk, Wv);
    attn_kernel<<<BB * 4, 256>>>(x, scale, bq, bk, bv, out);
    rmsnorm_kernel<<<BB, 256>>>(out, nw);
}

// round 9
// speedup vs baseline: 1.6648x; 1.0310x over previous
#include <cuda_runtime.h>

#define BB 256
#define DD 1024
#define LOG2E 1.4426950408889634f
#define NSPLIT 6

// scratch: six split-K partial buffers for Q,K,V (3 MB each, ~19 MB total)
__device__ float g_P[NSPLIT * 3 * BB * DD];

__device__ __forceinline__ float ex2f(float x) {
    float y; asm("ex2.approx.ftz.f32 %0, %1;" : "=f"(y) : "f"(x)); return y;
}
__device__ __forceinline__ unsigned long long pk2(float lo, float hi) {
    unsigned long long r; asm("mov.b64 %0, {%1,%2};" : "=l"(r) : "f"(lo), "f"(hi)); return r;
}
__device__ __forceinline__ void upk2(unsigned long long v, float &lo, float &hi) {
    asm("mov.b64 {%0,%1}, %2;" : "=f"(lo), "=f"(hi) : "l"(v));
}
__device__ __forceinline__ unsigned long long ffma2(unsigned long long a, unsigned long long b, unsigned long long c) {
    unsigned long long d;
    asm("fma.rn.f32x2 %0, %1, %2, %3;" : "=l"(d) : "l"(a), "l"(b), "l"(c));
    return d;
}

// ---------------------------------------------------------------------------
// Kernel 1: QKV partial GEMMs, split-K=6 (176x4 + 160x2).
// Tile 128(m) x 128(n) x 16(k), 256 threads, 8m x 8n per thread via FFMA2.
// grid = (2, 8, 18): z = ks*3 + gemm_id -> 288 blocks, 2 blocks/SM resident
// (16 warps/SM) in a single wave.
// ---------------------------------------------------------------------------
#define TM 128
#define TN 128
#define TK 16
#define GTH 256

__global__ __launch_bounds__(GTH, 2) void gemm_qkv_kernel(
    const float* __restrict__ x,
    const float* __restrict__ Wq,
    const float* __restrict__ Wk,
    const float* __restrict__ Wv)
{
    const int z  = blockIdx.z;
    const int g  = z % 3;        // 0=Q, 1=K, 2=V
    const int ks = z / 3;        // k-split index 0..5
    const float* W = (g == 0) ? Wq : (g == 1) ? Wk : Wv;
    float* out = g_P + ks * (3 * BB * DD) + g * (BB * DD);
    const int k0 = (ks < 4) ? ks * 176 : 704 + (ks - 4) * 160;
    const int NT = (ks < 4) ? 11 : 10;   // k-tiles of 16

    __shared__ __align__(16) float xs[2][TK][TM];  // 16KB
    __shared__ __align__(16) float ws[2][TK][TN];  // 16KB

    const int t  = threadIdx.x;
    const int m0 = blockIdx.x * TM;
    const int n0 = blockIdx.y * TN;

    // loaders: 256 threads fill 128 rows x 16 k (8 consecutive k per thread)
    const int lr  = t & 127;           // row (m for x, n for W)
    const int lk0 = (t >> 7) * 8;      // 0 or 8

    // compute map: 16(tx) x 16(ty); per-thread n = tx*4..+3 & 64+tx*4..+3,
    //                               per-thread m = ty*4..+3 & 64+ty*4..+3
    const int tx = t & 15;
    const int ty = t >> 4;

    unsigned long long acc[8][4];
#pragma unroll
    for (int i = 0; i < 8; i++)
#pragma unroll
        for (int j = 0; j < 4; j++) acc[i][j] = pk2(0.f, 0.f);

    const float* xp = &x[(m0 + lr) * DD + k0 + lk0];
    const float* wp = &W[(n0 + lr) * DD + k0 + lk0];

    float4 ax0, ax1, aw0, aw1;
    ax0 = *(const float4*)(xp);  ax1 = *(const float4*)(xp + 4);
    aw0 = *(const float4*)(wp);  aw1 = *(const float4*)(wp + 4);

    int buf = 0;
#pragma unroll
    for (int j = 0; j < 4; j++) {
        xs[0][lk0 + j][lr]     = ((const float*)&ax0)[j];
        xs[0][lk0 + 4 + j][lr] = ((const float*)&ax1)[j];
        ws[0][lk0 + j][lr]     = ((const float*)&aw0)[j];
        ws[0][lk0 + 4 + j][lr] = ((const float*)&aw1)[j];
    }
    __syncthreads();

    for (int kt = 0; kt < NT; kt++) {
        if (kt + 1 < NT) {
            const float* px = xp + (kt + 1) * TK;
            const float* pw = wp + (kt + 1) * TK;
            ax0 = *(const float4*)(px);  ax1 = *(const float4*)(px + 4);
            aw0 = *(const float4*)(pw);  aw1 = *(const float4*)(pw + 4);
        }
#pragma unroll
        for (int kk = 0; kk < TK; kk++) {
            float4 a0 = *(const float4*)&xs[buf][kk][ty * 4];
            float4 a1 = *(const float4*)&xs[buf][kk][64 + ty * 4];
            ulonglong2 b0 = *(const ulonglong2*)&ws[buf][kk][tx * 4];       // (b0,b1),(b2,b3)
            ulonglong2 b1 = *(const ulonglong2*)&ws[buf][kk][64 + tx * 4];
            unsigned long long ad[8];
            ad[0] = pk2(a0.x, a0.x); ad[1] = pk2(a0.y, a0.y);
            ad[2] = pk2(a0.z, a0.z); ad[3] = pk2(a0.w, a0.w);
            ad[4] = pk2(a1.x, a1.x); ad[5] = pk2(a1.y, a1.y);
            ad[6] = pk2(a1.z, a1.z); ad[7] = pk2(a1.w, a1.w);
#pragma unroll
            for (int mi = 0; mi < 8; mi++) {
                acc[mi][0] = ffma2(ad[mi], b0.x, acc[mi][0]);
                acc[mi][1] = ffma2(ad[mi], b0.y, acc[mi][1]);
                acc[mi][2] = ffma2(ad[mi], b1.x, acc[mi][2]);
                acc[mi][3] = ffma2(ad[mi], b1.y, acc[mi][3]);
            }
        }
        if (kt + 1 < NT) {
            __syncthreads();
            buf ^= 1;
#pragma unroll
            for (int j = 0; j < 4; j++) {
                xs[buf][lk0 + j][lr]     = ((const float*)&ax0)[j];
                xs[buf][lk0 + 4 + j][lr] = ((const float*)&ax1)[j];
                ws[buf][lk0 + j][lr]     = ((const float*)&aw0)[j];
                ws[buf][lk0 + 4 + j][lr] = ((const float*)&aw1)[j];
            }
            __syncthreads();
        }
    }

#pragma unroll
    for (int mi = 0; mi < 8; mi++) {
        const int row = m0 + ((mi < 4) ? (ty * 4 + mi) : (64 + ty * 4 + mi - 4));
        float r0, r1, r2, r3;
        float4 o;
        upk2(acc[mi][0], r0, r1);  upk2(acc[mi][1], r2, r3);
        o.x = r0; o.y = r1; o.z = r2; o.w = r3;
        *(float4*)&out[row * DD + n0 + tx * 4] = o;
        upk2(acc[mi][2], r0, r1);  upk2(acc[mi][3], r2, r3);
        o.x = r0; o.y = r1; o.z = r2; o.w = r3;
        *(float4*)&out[row * DD + n0 + 64 + tx * 4] = o;
    }
}

// ---------------------------------------------------------------------------
// Kernel 2: per-(b,i) scalar-softmax attention + residual.
// Fuses the 6-way split-K reduction and QKV bias adds into the load phase.
// grid = 1024 blocks (b x i-quarter), 256 threads; inner loop at MUFU roofline.
// ---------------------------------------------------------------------------
__global__ __launch_bounds__(256) void attn_kernel(
    const float* __restrict__ x,
    const float* __restrict__ scale_p,
    const float* __restrict__ bq,
    const float* __restrict__ bk,
    const float* __restrict__ bv,
    float* __restrict__ out)
{
    const int b     = blockIdx.x >> 2;
    const int ibase = (blockIdx.x & 3) << 8;
    const int t     = threadIdx.x;

    __shared__ float2 kv[DD];
    __shared__ float redmx[8], redmn[8];

    const int koff = BB * DD + b * DD;
    const int voff = 2 * BB * DD + b * DD;

    float mx = -1e30f, mn = 1e30f;
#pragma unroll
    for (int j = t; j < DD; j += 256) {
        float kx = bk[j];
        float vy = bv[j];
#pragma unroll
        for (int s = 0; s < NSPLIT; s++) {
            kx += g_P[s * (3 * BB * DD) + koff + j];
            vy += g_P[s * (3 * BB * DD) + voff + j];
        }
        kv[j] = make_float2(kx, vy);
        mx = fmaxf(mx, kx);
        mn = fminf(mn, kx);
    }
#pragma unroll
    for (int o = 16; o > 0; o >>= 1) {
        mx = fmaxf(mx, __shfl_xor_sync(0xFFFFFFFFu, mx, o));
        mn = fminf(mn, __shfl_xor_sync(0xFFFFFFFFu, mn, o));
    }
    if ((t & 31) == 0) { redmx[t >> 5] = mx; redmn[t >> 5] = mn; }
    __syncthreads();
    mx = redmx[0]; mn = redmn[0];
#pragma unroll
    for (int w = 1; w < 8; w++) { mx = fmaxf(mx, redmx[w]); mn = fminf(mn, redmn[w]); }

    const int   i   = ibase + t;
    const int   qi  = b * DD + i;
    float q = bq[i];
#pragma unroll
    for (int s = 0; s < NSPLIT; s++) q += g_P[s * (3 * BB * DD) + qi];

    const float cs  = LOG2E / scale_p[0];
    const float c2  = q * cs;                              // Q scaled into log2 domain
    const float m2  = (c2 >= 0.f) ? c2 * mx : c2 * mn;     // row max in log2 domain
    const float nm2 = -m2;

    float s  = 0.f;
    float dn = 0.f;
#pragma unroll 8
    for (int j = 0; j < DD; j++) {
        float2 kvj = kv[j];                        // broadcast LDS.64
        float  e   = ex2f(__fmaf_rn(c2, kvj.x, nm2));
        s  += e;
        dn  = __fmaf_rn(e, kvj.y, dn);
    }

    out[b * DD + i] = dn / s + x[b * DD + i];
}

// ---------------------------------------------------------------------------
// Kernel 3: in-place RMSNorm over each row of out. grid = 256, 256 threads.
// ---------------------------------------------------------------------------
__global__ __launch_bounds__(256) void rmsnorm_kernel(
    float* __restrict__ out, const float* __restrict__ nw)
{
    const int b = blockIdx.x;
    const int t = threadIdx.x;
    __shared__ float red[8];

    float4 h = *(const float4*)&out[b * DD + t * 4];
    float local = h.x * h.x + h.y * h.y + h.z * h.z + h.w * h.w;
#pragma unroll
    for (int o = 16; o > 0; o >>= 1) local += __shfl_xor_sync(0xFFFFFFFFu, local, o);
    if ((t & 31) == 0) red[t >> 5] = local;
    __syncthreads();
    float tot = 0.f;
#pragma unroll
    for (int w = 0; w < 8; w++) tot += red[w];

    float r = rsqrtf(tot * (1.0f / DD) + 1e-6f);
    float4 w4 = *(const float4*)&nw[t * 4];
    float4 o;
    o.x = h.x * r * w4.x;
    o.y = h.y * r * w4.y;
    o.z = h.z * r * w4.z;
    o.w = h.w * r * w4.w;
    *(float4*)&out[b * DD + t * 4] = o;
}

extern "C" void kernel_launch(void* const* d_in, const int* in_sizes, int n_in,
                              void* d_out, int out_size)
{
    const float* x     = (const float*)d_in[0];
    const float* Wq    = (const float*)d_in[1];
    const float* bq    = (const float*)d_in[2];
    const float* Wk    = (const float*)d_in[3];
    const float* bk    = (const float*)d_in[4];
    const float* Wv    = (const float*)d_in[5];
    const float* bv    = (const float*)d_in[6];
    const float* scale = (const float*)d_in[7];
    const float* nw    = (const float*)d_in[8];
    float* out = (float*)d_out;

    dim3 ggrid(BB / TM, DD / TN, 3 * NSPLIT);   // z = ks*3 + gemm_id
    gemm_qkv_kernel<<<ggrid, GTH>>>(x, Wq, Wk, Wv);
    attn_kernel<<<BB * 4, 256>>>(x, scale, bq, bk, bv, out);
    rmsnorm_kernel<<<BB, 256>>>(out, nw);
}